// round 9
// baseline (speedup 1.0000x reference)
#include <cuda_runtime.h>
#include <cuda_bf16.h>
#include <math.h>
#include <stdint.h>

#define B_ROWS 16384
#define TOK 16
#define TPB 256

// ---------------- gmem scratch (static, allocation-free) ----------------
__device__ uint32_t g_xh[(size_t)TOK * B_ROWS * 64];   // [t][row][64] bf16x2 (hi)
__device__ uint32_t g_xl[(size_t)TOK * B_ROWS * 64];   // (lo)
__device__ uint32_t g_w1h[TOK * 512 * 64];             // [t][o=512][64] bf16x2
__device__ uint32_t g_w1l[TOK * 512 * 64];
__device__ uint32_t g_w2h[TOK * 128 * 256];            // [t][o=128][256] bf16x2
__device__ uint32_t g_w2l[TOK * 128 * 256];
__device__ float    g_yp[(size_t)TOK * B_ROWS * 128];  // [t][row][o] fp32

// ---------------- helpers ----------------
__device__ __forceinline__ uint32_t smem_to_u32(const void* p) {
    uint32_t a;
    asm("{ .reg .u64 t; cvta.to.shared.u64 t, %1; cvt.u32.u64 %0, t; }"
        : "=r"(a) : "l"(p));
    return a;
}
__device__ __forceinline__ void ldsm4(uint32_t r[4], uint32_t addr) {
    asm volatile("ldmatrix.sync.aligned.m8n8.x4.shared.b16 {%0,%1,%2,%3}, [%4];"
                 : "=r"(r[0]), "=r"(r[1]), "=r"(r[2]), "=r"(r[3]) : "r"(addr));
}
__device__ __forceinline__ void mma_bf16(float c[4], const uint32_t a[4],
                                         uint32_t b0, uint32_t b1) {
    asm volatile(
        "mma.sync.aligned.m16n8k16.row.col.f32.bf16.bf16.f32 "
        "{%0,%1,%2,%3}, {%4,%5,%6,%7}, {%8,%9}, {%0,%1,%2,%3};"
        : "+f"(c[0]), "+f"(c[1]), "+f"(c[2]), "+f"(c[3])
        : "r"(a[0]), "r"(a[1]), "r"(a[2]), "r"(a[3]), "r"(b0), "r"(b1));
}

#define CP_ASYNC16(dst, src) \
    asm volatile("cp.async.cg.shared.global [%0], [%1], 16;" :: "r"(dst), "l"(src))
#define CP_COMMIT() asm volatile("cp.async.commit_group;" ::: "memory")
#define CP_WAIT(n)  asm volatile("cp.async.wait_group %0;" :: "n"(n) : "memory")

__device__ __forceinline__ void split2(float f0, float f1, uint32_t& hh, uint32_t& ll) {
    __nv_bfloat16 h0 = __float2bfloat16(f0);
    __nv_bfloat16 h1 = __float2bfloat16(f1);
    float l0 = f0 - __bfloat162float(h0);
    float l1 = f1 - __bfloat162float(h1);
    __nv_bfloat16 m0 = __float2bfloat16(l0);
    __nv_bfloat16 m1 = __float2bfloat16(l1);
    hh = (uint32_t)__bfloat16_as_ushort(h0) | ((uint32_t)__bfloat16_as_ushort(h1) << 16);
    ll = (uint32_t)__bfloat16_as_ushort(m0) | ((uint32_t)__bfloat16_as_ushort(m1) << 16);
}

// exact-erf GELU: 11-term odd Taylor on |x|<=2 (err < 2.5e-6), erff tail
__device__ __forceinline__ float gelu_f(float x) {
    float z = 0.70710678118654752f * x;
    float r;
    if (fabsf(x) <= 2.0f) {
        float u = z * z;
        float p =              1.4807192e-8f;
        p = fmaf(p, u, -1.6365349e-7f);
        p = fmaf(p, u,  1.6462114e-6f);
        p = fmaf(p, u, -1.4925650e-5f);
        p = fmaf(p, u,  1.2055332e-4f);
        p = fmaf(p, u, -8.5483270e-4f);
        p = fmaf(p, u,  5.2239776e-3f);
        p = fmaf(p, u, -2.6866171e-2f);
        p = fmaf(p, u,  1.1283792e-1f);
        p = fmaf(p, u, -3.7612639e-1f);
        p = fmaf(p, u,  1.1283791671f);
        r = z * p;
    } else {
        r = erff(z);
    }
    return 0.5f * x * (1.0f + r);
}

// ---------------- permute + split kernels ----------------
__global__ void permute_x_split(const float* __restrict__ x) {
    __shared__ float s[128 * 17];
    const int row = blockIdx.x;
    const float* src = x + (size_t)row * 2048;
    for (int i = threadIdx.x; i < 2048; i += TPB) {
        int c = i >> 4, t = i & 15;
        s[c * 17 + t] = src[i];
    }
    __syncthreads();
    for (int i = threadIdx.x; i < 1024; i += TPB) {
        int t = i >> 6, cp = i & 63;
        float f0 = s[(2 * cp) * 17 + t];
        float f1 = s[(2 * cp + 1) * 17 + t];
        uint32_t hh, ll;
        split2(f0, f1, hh, ll);
        size_t o = ((size_t)t * B_ROWS + row) * 64 + cp;
        g_xh[o] = hh;
        g_xl[o] = ll;
    }
}

__global__ void permute_w1_split(const float* __restrict__ w) {
    int idx = blockIdx.x * TPB + threadIdx.x;       // 0 .. 512*64-1
    int o = idx >> 6, cp = idx & 63;
    const float* src = w + ((size_t)(o * 128 + 2 * cp)) * 16;
    float buf[32];
#pragma unroll
    for (int q = 0; q < 8; q++) {
        float4 v = *(const float4*)(src + q * 4);
        buf[q * 4 + 0] = v.x; buf[q * 4 + 1] = v.y;
        buf[q * 4 + 2] = v.z; buf[q * 4 + 3] = v.w;
    }
#pragma unroll
    for (int t = 0; t < TOK; t++) {
        uint32_t hh, ll;
        split2(buf[t], buf[16 + t], hh, ll);
        g_w1h[t * 32768 + idx] = hh;
        g_w1l[t * 32768 + idx] = ll;
    }
}

__global__ void permute_w2_split(const float* __restrict__ w) {
    int idx = blockIdx.x * TPB + threadIdx.x;       // 0 .. 128*256-1
    int o = idx >> 8, kp = idx & 255;
    const float* src = w + ((size_t)(o * 512 + 2 * kp)) * 16;
    float buf[32];
#pragma unroll
    for (int q = 0; q < 8; q++) {
        float4 v = *(const float4*)(src + q * 4);
        buf[q * 4 + 0] = v.x; buf[q * 4 + 1] = v.y;
        buf[q * 4 + 2] = v.z; buf[q * 4 + 3] = v.w;
    }
#pragma unroll
    for (int t = 0; t < TOK; t++) {
        uint32_t hh, ll;
        split2(buf[t], buf[16 + t], hh, ll);
        g_w2h[t * 32768 + idx] = hh;
        g_w2l[t * 32768 + idx] = ll;
    }
}

__global__ void permute_y_kernel(float* __restrict__ y) {
    __shared__ float s[128 * 17];
    const int row = blockIdx.x;
    for (int i = threadIdx.x; i < 2048; i += TPB) {
        int t = i >> 7, o = i & 127;
        s[o * 17 + t] = g_yp[((size_t)t * B_ROWS + row) * 128 + o];
    }
    __syncthreads();
    float* dst = y + (size_t)row * 2048;
    for (int i = threadIdx.x; i < 2048; i += TPB) {
        int o = i >> 4, t = i & 15;
        dst[i] = s[o * 17 + t];
    }
}

// ---------------- main 2-CTA/SM mma.sync FFN kernel (X in registers) ----------------
// M=64 rows/CTA, chunk=32 (16 chunks). Warp grid 4 rowg x 2 colg.
// X is staged to smem once, ldsm'd to registers (8 k-steps x hi/lo), then its
// smem region is reused for the W1 double buffers.
// smem (72KB/CTA, 2 CTAs resident):
//   W1 bufs: 0     + b*16384  (h +0 8K: 32r x 256B, l +8192)   [X staged here first]
//   W2 bufs: 32768 + b*16384  (128r x 128B, packed: h chunks0-3 | l chunks4-7)
//   H:       65536            (64r  x 128B, packed: h chunks0-3 | l chunks4-7)
#define SM_W1 0
#define SM_W2 32768
#define SM_H  65536
#define SM_TOTAL 73728

// W1 chunk j: 32 rows x 16 uint4 (pitch 256B, swizzled), h+l
__device__ __forceinline__ void cpa_w1(uint32_t sb, int buf,
                                       const uint4* __restrict__ h,
                                       const uint4* __restrict__ l, int tid) {
    uint32_t base = sb + SM_W1 + buf * 16384;
#pragma unroll
    for (int i = 0; i < 2; i++) {
        int lin = i * TPB + tid;          // 0..511
        int r = lin >> 4, c = lin & 15;
        uint32_t off = (uint32_t)r * 256 + (uint32_t)((c ^ (r & 7)) << 4);
        CP_ASYNC16(base + off, h + r * 16 + c);
        CP_ASYNC16(base + 8192 + off, l + r * 16 + c);
    }
}
// W2 chunk j: 128 rows x 4 uint4 each of h and l, packed into 128B rows.
__device__ __forceinline__ void cpa_w2(uint32_t sb, int buf,
                                       const uint4* __restrict__ h,
                                       const uint4* __restrict__ l, int tid) {
    uint32_t base = sb + SM_W2 + buf * 16384;
#pragma unroll
    for (int i = 0; i < 2; i++) {
        int lin = i * TPB + tid;          // 0..511
        int r = lin >> 2, c = lin & 3;
        uint32_t offh = (uint32_t)r * 128 + (uint32_t)((c ^ (r & 7)) << 4);
        uint32_t offl = (uint32_t)r * 128 + (uint32_t)(((c + 4) ^ (r & 7)) << 4);
        CP_ASYNC16(base + offh, h + r * 64 + c);
        CP_ASYNC16(base + offl, l + r * 64 + c);
    }
}

__global__ void __launch_bounds__(TPB, 2) ffn_mma_kernel() {
    extern __shared__ char smem[];
    const uint32_t sb = smem_to_u32(smem);
    const int tid = threadIdx.x;
    const int lane = tid & 31;
    const int wid = tid >> 5;
    const int rowg = wid >> 1;      // 0..3 : 16-row group
    const int colg = wid & 1;       // 0..1 : chunk-col half / out-col half
    const int bid = blockIdx.x;
    const int t = bid >> 8;         // 256 CTAs per t, adjacent -> weights L2-hot
    const int m0 = (bid & 255) * 64;

    const int rx = lane & 7;
    const int a_row16 = ((lane >> 3) & 1) * 8 + rx;
    const int a_cs = lane >> 4;             // 0/1
    const int b_row16 = ((lane >> 4) & 1) * 8 + rx;
    const int b_cs = (lane >> 3) & 1;       // 0/1

    const uint32_t aoffX = (uint32_t)(rowg * 16 + a_row16) * 256;
    const uint32_t aoffH = (uint32_t)(rowg * 16 + a_row16) * 128;
    const uint32_t boff1 = (uint32_t)(colg * 16 + b_row16) * 256;

    const uint4* w1h = (const uint4*)(g_w1h + (size_t)t * 32768);
    const uint4* w1l = (const uint4*)(g_w1l + (size_t)t * 32768);
    const uint4* w2h = (const uint4*)(g_w2h + (size_t)t * 32768);
    const uint4* w2l = (const uint4*)(g_w2l + (size_t)t * 32768);

    // ---- stage X once into (future) W1 region, ldsm to registers ----
    uint32_t xfh[8][4], xfl[8][4];
    {
        const uint4* xh = (const uint4*)(g_xh + ((size_t)t * B_ROWS + m0) * 64);
        const uint4* xl = (const uint4*)(g_xl + ((size_t)t * B_ROWS + m0) * 64);
#pragma unroll
        for (int i = 0; i < 4; i++) {
            int lin = i * TPB + tid;      // 0..1023 : 64 rows x 16 uint4
            int r = lin >> 4, c = lin & 15;
            uint32_t off = (uint32_t)r * 256 + (uint32_t)((c ^ (r & 7)) << 4);
            CP_ASYNC16(sb + off, xh + r * 16 + c);
            CP_ASYNC16(sb + 16384 + off, xl + r * 16 + c);
        }
        CP_COMMIT();
        CP_WAIT(0);
        __syncthreads();
#pragma unroll
        for (int k = 0; k < 8; k++) {
            uint32_t asw = (uint32_t)(((2 * k + a_cs) ^ rx) << 4);
            ldsm4(xfh[k], sb + aoffX + asw);
            ldsm4(xfl[k], sb + 16384 + aoffX + asw);
        }
        __syncthreads();   // all X reads done before W1 overwrites the region
        cpa_w1(sb, 0, w1h, w1l, tid);
        cpa_w2(sb, 0, w2h, w2l, tid);
        CP_COMMIT();
        CP_WAIT(0);
        __syncthreads();
    }

    // persistent GEMM2 accumulators: warp = 16 rows x 64 out-cols -> 8 n8-frags
    float c2[8][4];
#pragma unroll
    for (int n = 0; n < 8; n++)
#pragma unroll
        for (int q = 0; q < 4; q++) c2[n][q] = 0.0f;

    const int g = lane >> 2, tt = lane & 3;

    for (int j = 0; j < 16; j++) {
        const uint32_t w1b = sb + SM_W1 + (j & 1) * 16384;
        const uint32_t w2b = sb + SM_W2 + (j & 1) * 16384;

        if (j < 15) {
            cpa_w1(sb, (j + 1) & 1, w1h + (size_t)((j + 1) * 32) * 16,
                   w1l + (size_t)((j + 1) * 32) * 16, tid);
            cpa_w2(sb, (j + 1) & 1, w2h + (size_t)(j + 1) * 4,
                   w2l + (size_t)(j + 1) * 4, tid);
            CP_COMMIT();
        }

        // ---- GEMM1 (fused 3-pass): c1 = Xh*W1h + Xh*W1l + Xl*W1h ----
        float c1[2][4];
#pragma unroll
        for (int n = 0; n < 2; n++)
#pragma unroll
            for (int q = 0; q < 4; q++) c1[n][q] = 0.0f;

#pragma unroll
        for (int k = 0; k < 8; k++) {
            uint32_t bsw = (uint32_t)(((2 * k + b_cs) ^ rx) << 4);
            uint32_t bh[4], bl[4];
            ldsm4(bh, w1b + boff1 + bsw);
            ldsm4(bl, w1b + 8192 + boff1 + bsw);
            mma_bf16(c1[0], xfh[k], bh[0], bh[1]);
            mma_bf16(c1[0], xfh[k], bl[0], bl[1]);
            mma_bf16(c1[0], xfl[k], bh[0], bh[1]);
            mma_bf16(c1[1], xfh[k], bh[2], bh[3]);
            mma_bf16(c1[1], xfh[k], bl[2], bl[3]);
            mma_bf16(c1[1], xfl[k], bh[2], bh[3]);
        }

        // ---- GELU + split -> packed H tile (h chunks 0-3 | l chunks 4-7) ----
#pragma unroll
        for (int n = 0; n < 2; n++) {
            int col = colg * 16 + n * 8 + 2 * tt;   // 0..31 chunk k-col
            int ch = col >> 3, cb = (col & 7) * 2;
            int r0 = rowg * 16 + g;
            int r1 = r0 + 8;
            uint32_t hh, ll;
            split2(gelu_f(c1[n][0]), gelu_f(c1[n][1]), hh, ll);
            *(uint32_t*)(smem + SM_H + (uint32_t)r0 * 128 +
                         (uint32_t)((ch ^ (r0 & 7)) << 4) + cb) = hh;
            *(uint32_t*)(smem + SM_H + (uint32_t)r0 * 128 +
                         (uint32_t)(((ch + 4) ^ (r0 & 7)) << 4) + cb) = ll;
            split2(gelu_f(c1[n][2]), gelu_f(c1[n][3]), hh, ll);
            *(uint32_t*)(smem + SM_H + (uint32_t)r1 * 128 +
                         (uint32_t)((ch ^ (r1 & 7)) << 4) + cb) = hh;
            *(uint32_t*)(smem + SM_H + (uint32_t)r1 * 128 +
                         (uint32_t)(((ch + 4) ^ (r1 & 7)) << 4) + cb) = ll;
        }
        __syncthreads();     // H complete

        // ---- GEMM2 (fused 3-pass): c2 += Hh*W2h + Hh*W2l + Hl*W2h ----
#pragma unroll
        for (int k = 0; k < 2; k++) {
            int cha = 2 * k + a_cs;            // 0..3 (h); +4 for l
            int chb = 2 * k + b_cs;
            uint32_t ah[4], al[4];
            ldsm4(ah, sb + SM_H + aoffH + (uint32_t)((cha ^ rx) << 4));
            ldsm4(al, sb + SM_H + aoffH + (uint32_t)(((cha + 4) ^ rx) << 4));
#pragma unroll
            for (int grp = 0; grp < 4; grp++) {
                uint32_t boff = (uint32_t)(colg * 64 + grp * 16 + b_row16) * 128;
                uint32_t bh[4], bl[4];
                ldsm4(bh, w2b + boff + (uint32_t)((chb ^ rx) << 4));
                ldsm4(bl, w2b + boff + (uint32_t)(((chb + 4) ^ rx) << 4));
                mma_bf16(c2[grp * 2], ah, bh[0], bh[1]);
                mma_bf16(c2[grp * 2], ah, bl[0], bl[1]);
                mma_bf16(c2[grp * 2], al, bh[0], bh[1]);
                mma_bf16(c2[grp * 2 + 1], ah, bh[2], bh[3]);
                mma_bf16(c2[grp * 2 + 1], ah, bl[2], bl[3]);
                mma_bf16(c2[grp * 2 + 1], al, bh[2], bh[3]);
            }
        }

        if (j < 15) {
            CP_WAIT(0);
            __syncthreads();   // W(j+1) arrived; H/W readers done
        }
    }

    // ---- store C2 -> g_yp [t][row][128] ----
    {
        float* ybase = g_yp + ((size_t)t * B_ROWS + m0 + rowg * 16) * 128;
#pragma unroll
        for (int n = 0; n < 8; n++) {
            int col = colg * 64 + n * 8 + 2 * tt;
            *(float2*)(ybase + (size_t)g * 128 + col) =
                make_float2(c2[n][0], c2[n][1]);
            *(float2*)(ybase + (size_t)(g + 8) * 128 + col) =
                make_float2(c2[n][2], c2[n][3]);
        }
    }
}

// ---------------- launch ----------------
extern "C" void kernel_launch(void* const* d_in, const int* in_sizes, int n_in,
                              void* d_out, int out_size) {
    const float* x  = (const float*)d_in[0];
    const float* w1 = (const float*)d_in[1];
    const float* w2 = (const float*)d_in[2];
    float* y = (float*)d_out;
    (void)in_sizes; (void)n_in; (void)out_size;

    cudaFuncSetAttribute(ffn_mma_kernel,
                         cudaFuncAttributeMaxDynamicSharedMemorySize, SM_TOTAL);

    permute_x_split<<<B_ROWS, TPB>>>(x);
    permute_w1_split<<<(512 * 64) / TPB, TPB>>>(w1);
    permute_w2_split<<<(128 * 256) / TPB, TPB>>>(w2);
    ffn_mma_kernel<<<TOK * (B_ROWS / 64), TPB, SM_TOTAL>>>();
    permute_y_kernel<<<B_ROWS, TPB>>>(y);
}